// round 16
// baseline (speedup 1.0000x reference)
#include <cuda_runtime.h>
#include <cstdint>

#define NMAX 100000
#define EMAX 1000000

// ---------------- scratch (device globals: allocation-free rule) -------------
__device__ float g_xl[(size_t)NMAX * 128];
__device__ float g_xr[(size_t)NMAX * 128];
__device__ float g_h [(size_t)NMAX * 128];
__device__ int   g_deg[NMAX + 1];
__device__ int   g_off[NMAX + 1];
__device__ int   g_cur[NMAX];
__device__ int   g_csr[EMAX];

// ---------------- helpers ----------------------------------------------------
typedef unsigned long long u64;

__device__ __forceinline__ float lrelu(float v) { return v > 0.f ? v : 0.2f * v; }

__device__ __forceinline__ u64 pack_dup(float x) {
    u64 r; asm("mov.b64 %0, {%1, %1};" : "=l"(r) : "f"(x)); return r;
}
__device__ __forceinline__ void ffma2(u64& d, u64 a, u64 b) {
    asm("fma.rn.f32x2 %0, %1, %2, %0;" : "+l"(d) : "l"(a), "l"(b));
}
__device__ __forceinline__ float2 unpack2(u64 v) {
    float2 f; asm("mov.b64 {%0, %1}, %2;" : "=f"(f.x), "=f"(f.y) : "l"(v)); return f;
}
__device__ __forceinline__ u64 d2l(double d) { return __double_as_longlong(d); }

// tf32 split: x = hi + lo with both tf32-representable; error ~2^-22|x|
__device__ __forceinline__ void tf32split(float x, uint32_t& hi, uint32_t& lo) {
    asm("cvt.rna.tf32.f32 %0, %1;" : "=r"(hi) : "f"(x));
    float r = x - __uint_as_float(hi);
    asm("cvt.rna.tf32.f32 %0, %1;" : "=r"(lo) : "f"(r));
}

__device__ __forceinline__ void mma_tf32(float* c, const uint32_t* a,
                                         uint32_t b0, uint32_t b1) {
    asm volatile("mma.sync.aligned.m16n8k8.row.col.f32.tf32.tf32.f32 "
                 "{%0,%1,%2,%3}, {%4,%5,%6,%7}, {%8,%9}, {%0,%1,%2,%3};"
                 : "+f"(c[0]), "+f"(c[1]), "+f"(c[2]), "+f"(c[3])
                 : "r"(a[0]), "r"(a[1]), "r"(a[2]), "r"(a[3]),
                   "r"(b0), "r"(b1));
}

// ---------------- tf32 3x dual GEMM (layers 1 & 2, Jhalf=128) ----------------
// Block: 128 threads, 64 rows x 64 cols (coloff = blockIdx.y*64), full K=128.
// Warp w: rows [w*16, w*16+16), all 64 cols, via m16n8k8 mma, 3xTF32 precision.
#define XS3 132   // xs row stride (floats): bank = 4g+tig, conflict-free
#define WS3 72    // W row stride (floats):  bank = 8tig+g, conflict-free

__global__ __launch_bounds__(128, 3)
void gemm_tf32(const float* __restrict__ in, int N,
               const float* __restrict__ Wl, const float* __restrict__ bl,
               const float* __restrict__ Wr, const float* __restrict__ br,
               int Jhalf,
               float* __restrict__ xl, float* __restrict__ xr)
{
    extern __shared__ float sm[];
    float* Wt   = sm;               // [128][WS3]  k-major, 64 local cols
    float* bcol = Wt + 128 * WS3;   // [64]
    float* xs   = bcol + 64;        // [64][XS3]

    const int tid    = threadIdx.x;
    const int coloff = blockIdx.y * 64;

    for (int idx = tid; idx < 128 * 64; idx += 128) {
        int k = idx >> 6, jl = idx & 63;
        int j = coloff + jl;
        Wt[k * WS3 + jl] = (j < Jhalf) ? Wl[j * 128 + k] : Wr[(j - Jhalf) * 128 + k];
    }
    if (tid < 64) {
        int j = coloff + tid;
        bcol[tid] = (j < Jhalf) ? bl[j] : br[j - Jhalf];
    }
    __syncthreads();

    const int warp = tid >> 5, lane = tid & 31;
    const int g = lane >> 2, tig = lane & 3;

    // col routing for this block (64-col block lies entirely in one half)
    float* outbase = (coloff < Jhalf) ? xl : xr;
    const int jbase = (coloff < Jhalf) ? coloff : coloff - Jhalf;

    const float4* in4 = reinterpret_cast<const float4*>(in);
    const int ntiles = (N + 63) / 64;

    for (int tile = blockIdx.x; tile < ntiles; tile += gridDim.x) {
        const int r0 = tile * 64;

        for (int idx = tid; idx < 64 * 32; idx += 128) {
            int r = idx >> 5, q = idx & 31;
            int row = r0 + r;
            float4 v = (row < N) ? in4[(size_t)row * 32 + q]
                                 : make_float4(0.f, 0.f, 0.f, 0.f);
            *reinterpret_cast<float4*>(xs + r * XS3 + q * 4) = v;
        }
        __syncthreads();

        float c[8][4];
        #pragma unroll
        for (int nt = 0; nt < 8; nt++)
            #pragma unroll
            for (int i = 0; i < 4; i++) c[nt][i] = 0.f;

        const float* xw = xs + (warp * 16) * XS3;

        for (int k0 = 0; k0 < 128; k0 += 8) {
            // A fragment (rows g, g+8; k cols k0+tig, k0+tig+4)
            float a0f = xw[g * XS3 + k0 + tig];
            float a1f = xw[(g + 8) * XS3 + k0 + tig];
            float a2f = xw[g * XS3 + k0 + tig + 4];
            float a3f = xw[(g + 8) * XS3 + k0 + tig + 4];
            uint32_t ah[4], al[4];
            tf32split(a0f, ah[0], al[0]);
            tf32split(a1f, ah[1], al[1]);
            tf32split(a2f, ah[2], al[2]);
            tf32split(a3f, ah[3], al[3]);

            #pragma unroll
            for (int nt = 0; nt < 8; nt++) {
                float b0f = Wt[(k0 + tig) * WS3 + nt * 8 + g];
                float b1f = Wt[(k0 + tig + 4) * WS3 + nt * 8 + g];
                uint32_t bh0, bl0, bh1, bl1;
                tf32split(b0f, bh0, bl0);
                tf32split(b1f, bh1, bl1);
                mma_tf32(c[nt], ah, bh0, bh1);   // hi*hi
                mma_tf32(c[nt], ah, bl0, bl1);   // hi*lo
                mma_tf32(c[nt], al, bh0, bh1);   // lo*hi
            }
        }
        __syncthreads();   // xs reused next tile

        // epilogue: c0/c1 -> row rwg, cols 2tig,2tig+1; c2/c3 -> row rwg+8
        const int rwg = r0 + warp * 16 + g;
        #pragma unroll
        for (int nt = 0; nt < 8; nt++) {
            int jl = nt * 8 + 2 * tig;
            float b0 = bcol[jl], b1 = bcol[jl + 1];
            if (rwg < N) {
                float* op = outbase + (size_t)rwg * Jhalf + jbase + jl;
                op[0] = c[nt][0] + b0;
                op[1] = c[nt][1] + b1;
            }
            if (rwg + 8 < N) {
                float* op = outbase + (size_t)(rwg + 8) * Jhalf + jbase + jl;
                op[0] = c[nt][2] + b0;
                op[1] = c[nt][3] + b1;
            }
        }
    }
}

// ---------------- ffma2 dual GEMM (layer 3 only; unchanged, passing) ---------
template<int COLG, int ROWG, int MAXCTA>
__global__ __launch_bounds__(COLG * ROWG, MAXCTA)
void gemm_dual(const float* __restrict__ in, int N,
               const float* __restrict__ Wl, const float* __restrict__ bl,
               const float* __restrict__ Wr, const float* __restrict__ br,
               int Jhalf,
               float* __restrict__ xl, float* __restrict__ xr)
{
    constexpr int JB    = COLG * 8;
    constexpr int HALF  = COLG * 4;
    constexpr int RPT   = ROWG * 8;
    constexpr int KC    = 32;
    constexpr int XS    = KC + 4;
    extern __shared__ float sm[];
    float* Wt   = sm;
    float* bcol = Wt + 128 * JB;
    float* xs   = bcol + JB;

    const int tid    = threadIdx.x;
    const int nth    = blockDim.x;
    const int coloff = blockIdx.y * JB;

    for (int idx = tid; idx < 128 * JB; idx += nth) {
        int k = idx / JB, jl = idx % JB;
        int j = coloff + jl;
        Wt[idx] = (j < Jhalf) ? Wl[j * 128 + k] : Wr[(j - Jhalf) * 128 + k];
    }
    for (int jl = tid; jl < JB; jl += nth) {
        int j = coloff + jl;
        bcol[jl] = (j < Jhalf) ? bl[j] : br[j - Jhalf];
    }
    __syncthreads();

    const int cg = tid % COLG;
    const int rg = tid / COLG;
    const int ntiles = (N + RPT - 1) / RPT;
    const float4* in4 = reinterpret_cast<const float4*>(in);

    for (int tile = blockIdx.x; tile < ntiles; tile += gridDim.x) {
        const int r0 = tile * RPT;

        u64 acc2[8][4];
        #pragma unroll
        for (int r = 0; r < 8; r++)
            #pragma unroll
            for (int c = 0; c < 4; c++) acc2[r][c] = 0ull;

        const float* xsb = xs + (rg * 8) * XS + rg * 4;
        const float* wbA = Wt + cg * 4;
        const float* wbB = Wt + HALF + cg * 4;

        #pragma unroll
        for (int ch = 0; ch < 128 / KC; ch++) {
            for (int idx = tid; idx < RPT * (KC / 4); idx += nth) {
                int r = idx >> 3, q = idx & 7;
                int row = r0 + r;
                float4 v = (row < N) ? in4[(size_t)row * 32 + ch * (KC / 4) + q]
                                     : make_float4(0.f, 0.f, 0.f, 0.f);
                *reinterpret_cast<float4*>(xs + r * XS + (r >> 3) * 4 + q * 4) = v;
            }
            __syncthreads();

            const int kb = ch * KC;
            for (int k = 0; k < KC; k += 4) {
                float4 xv[8];
                #pragma unroll
                for (int r = 0; r < 8; r++)
                    xv[r] = *reinterpret_cast<const float4*>(xsb + r * XS + k);
                #pragma unroll
                for (int kk = 0; kk < 4; kk++) {
                    const int krow = (kb + k + kk) * JB;
                    double2 wA = *reinterpret_cast<const double2*>(wbA + krow);
                    double2 wB = *reinterpret_cast<const double2*>(wbB + krow);
                    u64 w0 = d2l(wA.x), w1 = d2l(wA.y);
                    u64 w2 = d2l(wB.x), w3 = d2l(wB.y);
                    #pragma unroll
                    for (int r = 0; r < 8; r++) {
                        float xk = (kk == 0) ? xv[r].x : (kk == 1) ? xv[r].y
                                 : (kk == 2) ? xv[r].z : xv[r].w;
                        u64 xx = pack_dup(xk);
                        ffma2(acc2[r][0], w0, xx);
                        ffma2(acc2[r][1], w1, xx);
                        ffma2(acc2[r][2], w2, xx);
                        ffma2(acc2[r][3], w3, xx);
                    }
                }
            }
            __syncthreads();
        }

        const int jA = coloff + cg * 4;
        const int jB = coloff + HALF + cg * 4;
        float4 bvA = *reinterpret_cast<const float4*>(bcol + cg * 4);
        float4 bvB = *reinterpret_cast<const float4*>(bcol + HALF + cg * 4);
        float* baseA; int joA;
        if (jA < Jhalf) { baseA = xl; joA = jA; } else { baseA = xr; joA = jA - Jhalf; }
        float* baseB; int joB;
        if (jB < Jhalf) { baseB = xl; joB = jB; } else { baseB = xr; joB = jB - Jhalf; }

        #pragma unroll
        for (int r = 0; r < 8; r++) {
            int row = r0 + rg * 8 + r;
            if (row < N) {
                float2 c0 = unpack2(acc2[r][0]);
                float2 c1 = unpack2(acc2[r][1]);
                float2 c2 = unpack2(acc2[r][2]);
                float2 c3 = unpack2(acc2[r][3]);
                *reinterpret_cast<float4*>(baseA + (size_t)row * Jhalf + joA) =
                    make_float4(c0.x + bvA.x, c0.y + bvA.y, c1.x + bvA.z, c1.y + bvA.w);
                *reinterpret_cast<float4*>(baseB + (size_t)row * Jhalf + joB) =
                    make_float4(c2.x + bvB.x, c2.y + bvB.y, c3.x + bvB.z, c3.y + bvB.w);
            }
        }
    }
}

// ---------------- CSR build: histogram -> scan -> scatter --------------------
__global__ void hist_deg(const int* __restrict__ ei, int E, int* __restrict__ deg)
{
    int e = blockIdx.x * blockDim.x + threadIdx.x;
    if (e < E) atomicAdd(&deg[ei[E + e]], 1);
}

__global__ void scan_off(const int* __restrict__ deg, int* __restrict__ off,
                         int* __restrict__ cur, int N)
{
    __shared__ int wsum[32];
    __shared__ int carry_s;
    int tid = threadIdx.x, lane = tid & 31, wid = tid >> 5;
    if (tid == 0) carry_s = 0;
    __syncthreads();
    for (int base = 0; base < N; base += 1024) {
        int i = base + tid;
        int v = (i < N) ? deg[i] : 0;
        int x = v;
        #pragma unroll
        for (int o = 1; o < 32; o <<= 1) {
            int t = __shfl_up_sync(0xffffffffu, x, o);
            if (lane >= o) x += t;
        }
        if (lane == 31) wsum[wid] = x;
        __syncthreads();
        if (wid == 0) {
            int y = wsum[lane];
            #pragma unroll
            for (int o = 1; o < 32; o <<= 1) {
                int t = __shfl_up_sync(0xffffffffu, y, o);
                if (lane >= o) y += t;
            }
            wsum[lane] = y;
        }
        __syncthreads();
        int wb = (wid > 0) ? wsum[wid - 1] : 0;
        int carry = carry_s;
        int excl = carry + wb + x - v;
        if (i < N) { off[i] = excl; cur[i] = excl; }
        __syncthreads();
        if (tid == 1023) carry_s = carry + wsum[31];
        __syncthreads();
    }
    if (threadIdx.x == 0) off[N] = carry_s;
}

__global__ void scatter_csr(const int* __restrict__ ei, int E,
                            int* __restrict__ cur, int* __restrict__ csr)
{
    int e = blockIdx.x * blockDim.x + threadIdx.x;
    if (e < E) {
        int d = ei[E + e];
        int pos = atomicAdd(&cur[d], 1);
        csr[pos] = ei[e];
    }
}

// ---------------- pull aggregation, H=4, C=32 (warp per dst) -----------------
template<bool DO_ELU>
__global__ void pull_h4(const float* __restrict__ xl, const float* __restrict__ xr,
                        const int* __restrict__ off, const int* __restrict__ csr,
                        const float* __restrict__ att, const float* __restrict__ bias,
                        float* __restrict__ out, int N)
{
    int w = (int)((blockIdx.x * (unsigned)blockDim.x + threadIdx.x) >> 5);
    if (w >= N) return;
    int lane = threadIdx.x & 31;
    float4 av  = *reinterpret_cast<const float4*>(att + lane * 4);
    float4 xr4 = *reinterpret_cast<const float4*>(xr + (size_t)w * 128 + lane * 4);
    float4 bv  = *reinterpret_cast<const float4*>(bias + lane * 4);

    float4 a = *reinterpret_cast<const float4*>(xl + (size_t)w * 128 + lane * 4);
    float p = lrelu(a.x + xr4.x) * av.x + lrelu(a.y + xr4.y) * av.y
            + lrelu(a.z + xr4.z) * av.z + lrelu(a.w + xr4.w) * av.w;
    p += __shfl_xor_sync(0xffffffffu, p, 1);
    p += __shfl_xor_sync(0xffffffffu, p, 2);
    p += __shfl_xor_sync(0xffffffffu, p, 4);
    float q = __expf(p);
    float4 acc = make_float4(q * a.x, q * a.y, q * a.z, q * a.w);
    float ssum = q;

    int beg = off[w], end = off[w + 1];
    float4 an = make_float4(0.f, 0.f, 0.f, 0.f);
    if (beg < end) {
        int s = csr[beg];
        an = *reinterpret_cast<const float4*>(xl + (size_t)s * 128 + lane * 4);
    }
    for (int i = beg; i < end; i++) {
        a = an;
        if (i + 1 < end) {
            int s = csr[i + 1];
            an = *reinterpret_cast<const float4*>(xl + (size_t)s * 128 + lane * 4);
        }
        p = lrelu(a.x + xr4.x) * av.x + lrelu(a.y + xr4.y) * av.y
          + lrelu(a.z + xr4.z) * av.z + lrelu(a.w + xr4.w) * av.w;
        p += __shfl_xor_sync(0xffffffffu, p, 1);
        p += __shfl_xor_sync(0xffffffffu, p, 2);
        p += __shfl_xor_sync(0xffffffffu, p, 4);
        q = __expf(p);
        acc.x += q * a.x; acc.y += q * a.y; acc.z += q * a.z; acc.w += q * a.w;
        ssum += q;
    }

    float inv = 1.f / ssum;
    float4 o = make_float4(acc.x * inv + bv.x, acc.y * inv + bv.y,
                           acc.z * inv + bv.z, acc.w * inv + bv.w);
    if (DO_ELU) {
        o.x = o.x > 0.f ? o.x : expm1f(o.x);
        o.y = o.y > 0.f ? o.y : expm1f(o.y);
        o.z = o.z > 0.f ? o.z : expm1f(o.z);
        o.w = o.w > 0.f ? o.w : expm1f(o.w);
    }
    *reinterpret_cast<float4*>(out + (size_t)w * 128 + lane * 4) = o;
}

// ---------------- pull aggregation, H=1, C=40 (2 dsts per warp) --------------
__global__ void pull_h1(const float* __restrict__ xl, const float* __restrict__ xr,
                        const int* __restrict__ off, const int* __restrict__ csr,
                        const float* __restrict__ att, const float* __restrict__ bias,
                        float* __restrict__ out, int N)
{
    unsigned gw = (blockIdx.x * (unsigned)blockDim.x + threadIdx.x) >> 5;
    int lane = threadIdx.x & 31;
    int grp  = lane >> 4;
    int gl   = lane & 15;
    int d = (int)(gw * 2) + grp;
    bool vd = (d < N);
    int dc = vd ? d : 0;
    bool al = vd && (gl < 10);

    float4 z = make_float4(0.f, 0.f, 0.f, 0.f);
    float4 t   = al ? *reinterpret_cast<const float4*>(att + gl * 4) : z;
    float4 xr4 = al ? *reinterpret_cast<const float4*>(xr + (size_t)dc * 40 + gl * 4) : z;
    float4 bv  = al ? *reinterpret_cast<const float4*>(bias + gl * 4) : z;

    float4 a = al ? *reinterpret_cast<const float4*>(xl + (size_t)dc * 40 + gl * 4) : z;
    float p = al ? (lrelu(a.x + xr4.x) * t.x + lrelu(a.y + xr4.y) * t.y
                  + lrelu(a.z + xr4.z) * t.z + lrelu(a.w + xr4.w) * t.w) : 0.f;
    p += __shfl_xor_sync(0xffffffffu, p, 8);
    p += __shfl_xor_sync(0xffffffffu, p, 4);
    p += __shfl_xor_sync(0xffffffffu, p, 2);
    p += __shfl_xor_sync(0xffffffffu, p, 1);
    float q = __expf(p);
    float4 acc = make_float4(q * a.x, q * a.y, q * a.z, q * a.w);
    float ssum = q;

    int beg = vd ? off[d] : 0;
    int end = vd ? off[d + 1] : 0;
    int cnt = end - beg;
    int other = __shfl_xor_sync(0xffffffffu, cnt, 16);
    int mx = cnt > other ? cnt : other;

    for (int j = 0; j < mx; j++) {
        bool act = (j < cnt);
        float4 aa = z;
        float pp = 0.f;
        if (act && gl < 10) {
            int s = csr[beg + j];
            aa = *reinterpret_cast<const float4*>(xl + (size_t)s * 40 + gl * 4);
            pp = lrelu(aa.x + xr4.x) * t.x + lrelu(aa.y + xr4.y) * t.y
               + lrelu(aa.z + xr4.z) * t.z + lrelu(aa.w + xr4.w) * t.w;
        }
        pp += __shfl_xor_sync(0xffffffffu, pp, 8);
        pp += __shfl_xor_sync(0xffffffffu, pp, 4);
        pp += __shfl_xor_sync(0xffffffffu, pp, 2);
        pp += __shfl_xor_sync(0xffffffffu, pp, 1);
        float qq = __expf(pp);
        if (act) {
            acc.x += qq * aa.x; acc.y += qq * aa.y;
            acc.z += qq * aa.z; acc.w += qq * aa.w;
            ssum += qq;
        }
    }

    if (al) {
        float inv = 1.f / ssum;
        float4 o = make_float4(acc.x * inv + bv.x, acc.y * inv + bv.y,
                               acc.z * inv + bv.z, acc.w * inv + bv.w);
        *reinterpret_cast<float4*>(out + (size_t)dc * 40 + gl * 4) = o;
    }
}

// ---------------- host orchestration ----------------------------------------
static inline int ceil_div(int a, int b) { return (a + b - 1) / b; }

extern "C" void kernel_launch(void* const* d_in, const int* in_sizes, int n_in,
                              void* d_out, int out_size)
{
    const float* x   = (const float*)d_in[0];
    const int*   ei  = (const int*)  d_in[1];
    const float* W1l = (const float*)d_in[2];
    const float* b1l = (const float*)d_in[3];
    const float* W1r = (const float*)d_in[4];
    const float* b1r = (const float*)d_in[5];
    const float* at1 = (const float*)d_in[6];
    const float* bs1 = (const float*)d_in[7];
    const float* W2l = (const float*)d_in[8];
    const float* b2l = (const float*)d_in[9];
    const float* W2r = (const float*)d_in[10];
    const float* b2r = (const float*)d_in[11];
    const float* at2 = (const float*)d_in[12];
    const float* bs2 = (const float*)d_in[13];
    const float* W3l = (const float*)d_in[14];
    const float* b3l = (const float*)d_in[15];
    const float* W3r = (const float*)d_in[16];
    const float* b3r = (const float*)d_in[17];
    const float* at3 = (const float*)d_in[18];
    const float* bs3 = (const float*)d_in[19];
    float* out = (float*)d_out;

    const int N  = in_sizes[0] / 128;
    const int E  = in_sizes[1] / 2;

    float *xl, *xr, *h;
    int *deg, *off, *cur, *csr;
    cudaGetSymbolAddress((void**)&xl,  g_xl);
    cudaGetSymbolAddress((void**)&xr,  g_xr);
    cudaGetSymbolAddress((void**)&h,   g_h);
    cudaGetSymbolAddress((void**)&deg, g_deg);
    cudaGetSymbolAddress((void**)&off, g_off);
    cudaGetSymbolAddress((void**)&cur, g_cur);
    cudaGetSymbolAddress((void**)&csr, g_csr);

    // gemm_tf32: W 128*72 + bias 64 + xs 64*132 = 70912 B -> 3 CTA/SM
    const int SMT = (128 * WS3 + 64 + 64 * XS3) * 4;
    const int SM3 = (128 * 80 + 80 + (128 * 36 + 64)) * 4;   // 59968 B
    cudaFuncSetAttribute(gemm_tf32, cudaFuncAttributeMaxDynamicSharedMemorySize, SMT);
    cudaFuncSetAttribute(gemm_dual<10, 16, 2>, cudaFuncAttributeMaxDynamicSharedMemorySize, SM3);

    const dim3 gT(111, 4);    // 444 blocks = 3/SM, 4 col-splits of 64
    const dim3 g3(296, 1);

    // ===== CSR build (reused by all 3 layers) =====
    cudaMemsetAsync(deg, 0, (size_t)N * sizeof(int));
    hist_deg<<<ceil_div(E, 256), 256>>>(ei, E, deg);
    scan_off<<<1, 1024>>>(deg, off, cur, N);
    scatter_csr<<<ceil_div(E, 256), 256>>>(ei, E, cur, csr);

    const int pullBlocks4 = ceil_div(N * 32, 256);
    const int pullBlocks1 = ceil_div(ceil_div(N, 2) * 32, 256);

    // ===== layer 1 (H=4, C=32) =====
    gemm_tf32<<<gT, 128, SMT>>>(x, N, W1l, b1l, W1r, b1r, 128, xl, xr);
    pull_h4<true><<<pullBlocks4, 256>>>(xl, xr, off, csr, at1, bs1, h, N);

    // ===== layer 2 (H=4, C=32) =====
    gemm_tf32<<<gT, 128, SMT>>>(h, N, W2l, b2l, W2r, b2r, 128, xl, xr);
    pull_h4<true><<<pullBlocks4, 256>>>(xl, xr, off, csr, at2, bs2, h, N);

    // ===== layer 3 (H=1, C=40) =====
    gemm_dual<10, 16, 2><<<g3, 160, SM3>>>(h, N, W3l, b3l, W3r, b3r, 40, xl, xr);
    pull_h1<<<pullBlocks1, 256>>>(xl, xr, off, csr, at3, bs3, out, N);
}